// round 2
// baseline (speedup 1.0000x reference)
#include <cuda_runtime.h>
#include <math.h>

// Fixed problem shapes
#define BH 32            // B*H
#define LL 2048
#define DD 64
#define UU 40            // top-k count
#define SK 40            // sample_k
#define NS 32            // key-chunks for split softmax
#define CK 64            // keys per chunk (NS*CK == LL)
#define NCH 4            // K chunks for m-kernel staging
#define CROWS 512        // rows per staged chunk (NCH*CROWS == LL)
#define QPB 512          // queries per m-kernel block

// Scratch (device globals; no allocation allowed)
__device__ float g_M[BH * LL];
__device__ int   g_top[BH * UU];
__device__ float g_pm[BH * UU * NS];
__device__ float g_pl[BH * UU * NS];
__device__ float g_pacc[BH * UU * NS * DD];   // ~10.5 MB
__device__ int   g_sidx[LL * SK];             // samples reordered by chunk (local row)
__device__ int   g_soff[LL * (NCH + 1)];      // per-q chunk offsets

// ---------------------------------------------------------------------------
// Kernel 0: bucket each query's samples by 512-row chunk (idx shared over bh).
// grid = LL/256, block = 256, thread per query.
// ---------------------------------------------------------------------------
__global__ void sort_samples_kernel(const int* __restrict__ idxs) {
    const int q = blockIdx.x * 256 + threadIdx.x;
    int v[SK];
    int cnt[NCH] = {0, 0, 0, 0};
#pragma unroll
    for (int s = 0; s < SK; s++) {
        v[s] = __ldg(idxs + q * SK + s);
        cnt[v[s] >> 9]++;
    }
    int off[NCH + 1];
    off[0] = 0;
#pragma unroll
    for (int c = 0; c < NCH; c++) off[c + 1] = off[c] + cnt[c];
    int w[NCH];
#pragma unroll
    for (int c = 0; c < NCH; c++) w[c] = off[c];
#pragma unroll
    for (int s = 0; s < SK; s++) {
        const int c = v[s] >> 9;
        g_sidx[q * SK + (w[c]++)] = v[s] & (CROWS - 1);   // local row in chunk
    }
#pragma unroll
    for (int c = 0; c <= NCH; c++) g_soff[q * (NCH + 1) + c] = off[c];
}

// ---------------------------------------------------------------------------
// Kernel 1: cumsum of values along L, written to d_out.
// grid = BH*4 (16-dim groups), block = 1024 (16 d-lanes x 64 chunks of 32 rows)
// ---------------------------------------------------------------------------
__global__ void cumsum_kernel(const float* __restrict__ V, float* __restrict__ out) {
    const int bh    = blockIdx.x >> 2;
    const int dg    = blockIdx.x & 3;
    const int dl    = threadIdx.x & 15;
    const int d     = dg * 16 + dl;
    const int chunk = threadIdx.x >> 4;     // 0..63
    const int RPC   = 32;
    const size_t base = (size_t)bh * LL * DD;
    const float* vp = V + base + (size_t)chunk * RPC * DD + d;

    float s = 0.f;
#pragma unroll 8
    for (int i = 0; i < RPC; i++) s += vp[(size_t)i * DD];

    __shared__ float cs[64 * 16];
    cs[chunk * 16 + dl] = s;
    __syncthreads();

    float off = 0.f;
    for (int c = 0; c < chunk; c++) off += cs[c * 16 + dl];

    float* op = out + base + (size_t)chunk * RPC * DD + d;
    float acc = off;
#pragma unroll 8
    for (int i = 0; i < RPC; i++) {
        acc += vp[(size_t)i * DD];
        op[(size_t)i * DD] = acc;
    }
}

// ---------------------------------------------------------------------------
// Kernel 2: M[bh,q] = max_s(QK_s) - sum_s(QK_s)/L, smem-staged gather.
// grid = BH * (LL/QPB) = 128, block = 512 (16 warps, warp handles 32 queries).
// dynamic smem: CROWS*DD floats (128 KB).
// ---------------------------------------------------------------------------
__global__ void m2_kernel(const float* __restrict__ Q, const float* __restrict__ K) {
    extern __shared__ float Kc[];                 // [CROWS][DD]
    __shared__ float mS[QPB];
    __shared__ float sS[QPB];

    const int bh = blockIdx.x >> 2;               // LL/QPB == 4
    const int qb = blockIdx.x & 3;
    const int q0 = qb * QPB;
    const size_t base = (size_t)bh * LL * DD;
    const int tid  = threadIdx.x;
    const int warp = tid >> 5;
    const int lane = tid & 31;
    const int half = lane >> 4;                   // 0: sample j, 1: sample j+1
    const int hl   = lane & 15;                   // dim-group within half

    for (int i = tid; i < QPB; i += 512) { mS[i] = -INFINITY; sS[i] = 0.f; }

    for (int c = 0; c < NCH; c++) {
        __syncthreads();
        // stage chunk c of K
        const float4* src = (const float4*)(K + base + (size_t)c * CROWS * DD);
        float4* dst = (float4*)Kc;
#pragma unroll
        for (int i = 0; i < (CROWS * DD / 4) / 512; i++)
            dst[i * 512 + tid] = __ldg(src + i * 512 + tid);
        __syncthreads();

        for (int qi = 0; qi < 32; qi++) {
            const int q  = q0 + warp * 32 + qi;
            const float4 qv = __ldg((const float4*)(Q + base + (size_t)q * DD) + hl);
            const int jb = g_soff[q * (NCH + 1) + c];
            const int je = g_soff[q * (NCH + 1) + c + 1];
            float lm = -INFINITY, ls = 0.f;
            for (int j = jb; j < je; j += 2) {
                const int  sj    = j + half;
                const bool valid = sj < je;
                const int  r     = valid ? g_sidx[q * SK + sj] : 0;
                const float4 kv  = *(const float4*)(Kc + r * DD + hl * 4);
                float d = qv.x * kv.x + qv.y * kv.y + qv.z * kv.z + qv.w * kv.w;
#pragma unroll
                for (int o = 1; o < 16; o <<= 1) d += __shfl_xor_sync(0xffffffffu, d, o);
                const float cross = __shfl_xor_sync(0xffffffffu, d, 16);
                const float vA = half ? cross : d;
                const float vB = half ? d : cross;
                lm = fmaxf(lm, vA);
                ls += vA;
                if (j + 1 < je) { lm = fmaxf(lm, vB); ls += vB; }
            }
            if (lane == 0 && jb < je) {
                const int qq = warp * 32 + qi;
                mS[qq] = fmaxf(mS[qq], lm);
                sS[qq] += ls;
            }
        }
    }
    __syncthreads();
    for (int i = tid; i < QPB; i += 512)
        g_M[bh * LL + q0 + i] = mS[i] - sS[i] * (1.0f / (float)LL);
}

// ---------------------------------------------------------------------------
// Kernel 3: top-40 indices of M per (b,h). grid = BH, block = 256.
// ---------------------------------------------------------------------------
__global__ void topk_kernel() {
    const int bh = blockIdx.x;
    const int t  = threadIdx.x;
    __shared__ float sM[LL];
    __shared__ float wv[8];
    __shared__ int   wi[8];

    for (int i = t; i < LL; i += 256) sM[i] = g_M[bh * LL + i];
    __syncthreads();

    for (int it = 0; it < UU; it++) {
        float bv = -INFINITY; int bi = 0x7fffffff;
        for (int i = t; i < LL; i += 256) {
            float v = sM[i];
            if (v > bv || (v == bv && i < bi)) { bv = v; bi = i; }
        }
#pragma unroll
        for (int off = 16; off; off >>= 1) {
            float ov = __shfl_xor_sync(0xffffffffu, bv, off);
            int   oi = __shfl_xor_sync(0xffffffffu, bi, off);
            if (ov > bv || (ov == bv && oi < bi)) { bv = ov; bi = oi; }
        }
        if ((t & 31) == 0) { wv[t >> 5] = bv; wi[t >> 5] = bi; }
        __syncthreads();
        if (t == 0) {
            float fb = wv[0]; int fi = wi[0];
            for (int ww = 1; ww < 8; ww++)
                if (wv[ww] > fb || (wv[ww] == fb && wi[ww] < fi)) { fb = wv[ww]; fi = wi[ww]; }
            g_top[bh * UU + it] = fi;
            sM[fi] = -INFINITY;
        }
        __syncthreads();
    }
}

// ---------------------------------------------------------------------------
// Kernel 4: split-K attention partials. K row + V column live in registers.
// grid = BH*NS, block = CK (=64). Thread t = key (k0+t) in score phase,
// dim t in PV phase.
// ---------------------------------------------------------------------------
__global__ void __launch_bounds__(CK) attn_partial_kernel(const float* __restrict__ Q,
                                                          const float* __restrict__ K,
                                                          const float* __restrict__ V) {
    const int bh = blockIdx.x >> 5;
    const int c  = blockIdx.x & 31;
    const int t    = threadIdx.x;     // 0..63
    const int lane = t & 31;
    const int wid  = t >> 5;          // 0..1
    const size_t base = (size_t)bh * LL * DD;
    const int k0 = c * CK;

    // K row of key (k0+t) -> registers
    float4 kreg[16];
    const float4* kp = (const float4*)(K + base + (size_t)(k0 + t) * DD);
#pragma unroll
    for (int j = 0; j < 16; j++) kreg[j] = __ldg(kp + j);

    // V column of dim t -> registers (coalesced: for fixed k, warp reads 128B)
    float vreg[CK];
#pragma unroll
    for (int k = 0; k < CK; k++) vreg[k] = __ldg(V + base + (size_t)(k0 + k) * DD + t);

    __shared__ float Qs[DD];
    __shared__ float ps[CK];
    __shared__ float redm[2], redl[2];
    __shared__ int   topS[UU];
    if (t < UU) topS[t] = g_top[bh * UU + t];
    __syncthreads();

    for (int u = 0; u < UU; u++) {
        const int pos = topS[u];
        const int pi  = (bh * UU + u) * NS + c;
        if (k0 > pos) {   // fully masked chunk (uniform branch)
            if (t == 0) { g_pm[pi] = -INFINITY; g_pl[pi] = 0.f; }
            continue;
        }
        if (t < 16)
            *(float4*)&Qs[t * 4] = __ldg((const float4*)(Q + base + (size_t)pos * DD) + t);
        __syncthreads();   // A: Qs ready (prior iters' barriers make reuse safe)

        const int kg = k0 + t;
        float s;
        {
            float a0 = 0.f, a1 = 0.f, a2 = 0.f, a3 = 0.f;
#pragma unroll
            for (int j = 0; j < 16; j++) {
                const float4 kv = kreg[j];
                const float4 qv = *(const float4*)&Qs[j * 4];
                a0 += kv.x * qv.x; a1 += kv.y * qv.y;
                a2 += kv.z * qv.z; a3 += kv.w * qv.w;
            }
            s = ((a0 + a1) + (a2 + a3)) * 0.125f;   // 1/sqrt(64)
            if (kg > pos) s = -INFINITY;
        }

        float m = s;
#pragma unroll
        for (int off = 16; off; off >>= 1) m = fmaxf(m, __shfl_xor_sync(0xffffffffu, m, off));
        if (lane == 0) redm[wid] = m;
        __syncthreads();   // B
        m = fmaxf(redm[0], redm[1]);   // finite: key k0 is unmasked

        const float p = (kg <= pos) ? __expf(s - m) : 0.f;
        ps[t] = p;
        float l = p;
#pragma unroll
        for (int off = 16; off; off >>= 1) l += __shfl_xor_sync(0xffffffffu, l, off);
        if (lane == 0) redl[wid] = l;
        __syncthreads();   // C: ps visible
        l = redl[0] + redl[1];

        float acc = 0.f;
#pragma unroll
        for (int k = 0; k < CK; k++) acc += ps[k] * vreg[k];
        g_pacc[(size_t)pi * DD + t] = acc;
        if (t == 0) { g_pm[pi] = m; g_pl[pi] = l; }
    }
}

// ---------------------------------------------------------------------------
// Kernel 5: combine partials (log-sum-exp) and scatter into d_out.
// grid = BH*UU, block = 64 (thread = dim).
// ---------------------------------------------------------------------------
__global__ void combine_kernel(float* __restrict__ out) {
    const int bhu = blockIdx.x;
    const int t   = threadIdx.x;
    const int bh  = bhu / UU;
    const int pos = g_top[bhu];

    float mx = -INFINITY;
#pragma unroll
    for (int c = 0; c < NS; c++) mx = fmaxf(mx, g_pm[bhu * NS + c]);

    float Ls = 0.f, acc = 0.f;
#pragma unroll
    for (int c = 0; c < NS; c++) {
        const float plv = g_pl[bhu * NS + c];
        if (plv > 0.f) {
            const float w = __expf(g_pm[bhu * NS + c] - mx);
            Ls  += plv * w;
            acc += w * g_pacc[(size_t)(bhu * NS + c) * DD + t];
        }
    }
    out[(size_t)bh * LL * DD + (size_t)pos * DD + t] = acc / Ls;
}

// ---------------------------------------------------------------------------
extern "C" void kernel_launch(void* const* d_in, const int* in_sizes, int n_in,
                              void* d_out, int out_size) {
    const float* Q   = (const float*)d_in[0];
    const float* K   = (const float*)d_in[1];
    const float* V   = (const float*)d_in[2];
    const int*   idx = (const int*)d_in[3];
    float* out = (float*)d_out;

    const int m2_smem = CROWS * DD * sizeof(float);   // 128 KB
    cudaFuncSetAttribute(m2_kernel, cudaFuncAttributeMaxDynamicSharedMemorySize, m2_smem);

    sort_samples_kernel<<<LL / 256, 256>>>(idx);
    cumsum_kernel<<<BH * 4, 1024>>>(V, out);
    m2_kernel<<<BH * (LL / QPB), 512, m2_smem>>>(Q, K);
    topk_kernel<<<BH, 256>>>();
    attn_partial_kernel<<<BH * NS, CK>>>(Q, K, V);
    combine_kernel<<<BH * UU, DD>>>(out);
}

// round 3
// speedup vs baseline: 1.9038x; 1.9038x over previous
#include <cuda_runtime.h>
#include <math.h>

// Fixed problem shapes
#define BH 32            // B*H
#define LL 2048
#define DD 64
#define UU 40            // top-k count
#define SK 40            // sample_k
#define NS 32            // key-chunks for split softmax
#define CK 64            // keys per chunk (NS*CK == LL)

// Scratch (device globals; no allocation allowed)
__device__ float g_M[BH * LL];
__device__ int   g_top[BH * UU];
__device__ float g_pm[BH * UU * NS];
__device__ float g_pl[BH * UU * NS];
__device__ float g_pacc[BH * UU * NS * DD];   // ~10.5 MB

// ---------------------------------------------------------------------------
// Kernel 1: cumsum of values along L, written to d_out.
// grid = BH*4 (16-dim groups), block = 1024 (16 d-lanes x 64 chunks of 32 rows)
// ---------------------------------------------------------------------------
__global__ void cumsum_kernel(const float* __restrict__ V, float* __restrict__ out) {
    const int bh    = blockIdx.x >> 2;
    const int dg    = blockIdx.x & 3;
    const int dl    = threadIdx.x & 15;
    const int d     = dg * 16 + dl;
    const int chunk = threadIdx.x >> 4;     // 0..63
    const int RPC   = 32;
    const size_t base = (size_t)bh * LL * DD;
    const float* vp = V + base + (size_t)chunk * RPC * DD + d;

    float s = 0.f;
#pragma unroll 8
    for (int i = 0; i < RPC; i++) s += vp[(size_t)i * DD];

    __shared__ float cs[64 * 16];
    cs[chunk * 16 + dl] = s;
    __syncthreads();

    float off = 0.f;
    for (int c = 0; c < chunk; c++) off += cs[c * 16 + dl];

    float* op = out + base + (size_t)chunk * RPC * DD + d;
    float acc = off;
#pragma unroll 8
    for (int i = 0; i < RPC; i++) {
        acc += vp[(size_t)i * DD];
        op[(size_t)i * DD] = acc;
    }
}

// ---------------------------------------------------------------------------
// Kernel 2: sparsity metric M[bh, q] = max_s(QK_s) - sum_s(QK_s)/L
// One warp per query. grid = BH*LL/8 blocks of 256 threads (8 warps).
// (round-1 version: latency hidden by warp abundance, L2-BW bound)
// ---------------------------------------------------------------------------
__global__ void m_kernel(const float* __restrict__ Q, const float* __restrict__ K,
                         const int* __restrict__ idxs) {
    const int w    = blockIdx.x * 8 + (threadIdx.x >> 5);
    const int lane = threadIdx.x & 31;
    const int bh   = w >> 11;        // / 2048
    const int q    = w & (LL - 1);
    const size_t base = (size_t)bh * LL * DD;

    const float q0 = __ldg(Q + base + (size_t)q * DD + lane);
    const float q1 = __ldg(Q + base + (size_t)q * DD + 32 + lane);

    float mx = -INFINITY, sm = 0.f;
    const int* ip = idxs + q * SK;
#pragma unroll 4
    for (int s = 0; s < SK; s++) {
        const int idx = __ldg(ip + s);
        const float k0 = __ldg(K + base + (size_t)idx * DD + lane);
        const float k1 = __ldg(K + base + (size_t)idx * DD + 32 + lane);
        float p = q0 * k0 + q1 * k1;
#pragma unroll
        for (int off = 16; off; off >>= 1) p += __shfl_xor_sync(0xffffffffu, p, off);
        mx = fmaxf(mx, p);
        sm += p;
    }
    if (lane == 0) g_M[bh * LL + q] = mx - sm * (1.0f / (float)LL);
}

// ---------------------------------------------------------------------------
// Kernel 3: top-40 of M per (b,h). grid = BH, block = 256 (8 warps).
// Stage A: each warp extracts sorted local top-40 of its 256-element segment
//          entirely with registers + shfl (no block syncs).
// Stage B: warp 0 merges the 8 sorted lists.
// ---------------------------------------------------------------------------
__global__ void topk_kernel() {
    const int bh   = blockIdx.x;
    const int t    = threadIdx.x;
    const int warp = t >> 5;
    const int lane = t & 31;

    __shared__ float cv[8][UU];
    __shared__ int   ci[8][UU];

    // each lane owns 8 contiguous elements
    const int ebase = warp * 256 + lane * 8;
    float v[8];
#pragma unroll
    for (int j = 0; j < 8; j++) v[j] = g_M[bh * LL + ebase + j];

    for (int it = 0; it < UU; it++) {
        float bv = -INFINITY; int bj = 0;
#pragma unroll
        for (int j = 0; j < 8; j++)
            if (v[j] > bv) { bv = v[j]; bj = j; }   // ties: lowest j kept
        int bidx = ebase + bj;
#pragma unroll
        for (int off = 16; off; off >>= 1) {
            float ov = __shfl_xor_sync(0xffffffffu, bv, off);
            int   oi = __shfl_xor_sync(0xffffffffu, bidx, off);
            if (ov > bv || (ov == bv && oi < bidx)) { bv = ov; bidx = oi; }
        }
        // owner lane clears the winner
        if (bidx >= ebase && bidx < ebase + 8) v[bidx - ebase] = -INFINITY;
        if (lane == 0) { cv[warp][it] = bv; ci[warp][it] = bidx; }
    }
    __syncthreads();

    if (warp == 0) {
        int p = 0;   // head pointer for list `lane` (lanes 0..7)
        for (int it = 0; it < UU; it++) {
            float hv = (lane < 8) ? cv[lane][p] : -INFINITY;
            int   hi = (lane < 8) ? ci[lane][p] : 0x7fffffff;
            float wv = hv; int wi = hi;
#pragma unroll
            for (int off = 4; off; off >>= 1) {
                float ov = __shfl_xor_sync(0xffffffffu, wv, off);
                int   oi = __shfl_xor_sync(0xffffffffu, wi, off);
                if (ov > wv || (ov == wv && oi < wi)) { wv = ov; wi = oi; }
            }
            wv = __shfl_sync(0xffffffffu, wv, 0);
            wi = __shfl_sync(0xffffffffu, wi, 0);
            if (lane < 8 && hi == wi) p++;   // winner list advances
            if (lane == 0) g_top[bh * UU + it] = wi;
        }
    }
}

// ---------------------------------------------------------------------------
// Kernel 4: split-K attention partials. K row + V column in registers,
// all 40 Q rows preloaded to smem, ps double-buffered (2 bars/query).
// grid = BH*NS, block = CK (=64).
// ---------------------------------------------------------------------------
__global__ void __launch_bounds__(CK) attn_partial_kernel(const float* __restrict__ Q,
                                                          const float* __restrict__ K,
                                                          const float* __restrict__ V) {
    const int bh = blockIdx.x >> 5;
    const int c  = blockIdx.x & 31;
    const int t    = threadIdx.x;     // 0..63
    const int lane = t & 31;
    const int wid  = t >> 5;          // 0..1
    const size_t base = (size_t)bh * LL * DD;
    const int k0 = c * CK;

    // K row of key (k0+t) -> registers
    float4 kreg[16];
    const float4* kp = (const float4*)(K + base + (size_t)(k0 + t) * DD);
#pragma unroll
    for (int j = 0; j < 16; j++) kreg[j] = __ldg(kp + j);

    // V column of dim t -> registers
    float vreg[CK];
#pragma unroll
    for (int k = 0; k < CK; k++) vreg[k] = __ldg(V + base + (size_t)(k0 + k) * DD + t);

    __shared__ int   topS[UU];
    __shared__ float Qs[UU][DD];
    __shared__ float ps[2][CK];
    __shared__ float redm[2], redl[2];

    if (t < UU) topS[t] = g_top[bh * UU + t];
    __syncthreads();
    // preload all 40 Q rows (640 float4 loads across 64 threads)
    for (int i = t; i < UU * 16; i += CK) {
        const int u = i >> 4, j = i & 15;
        *(float4*)&Qs[u][j * 4] = __ldg((const float4*)(Q + base + (size_t)topS[u] * DD) + j);
    }
    __syncthreads();

    for (int u = 0; u < UU; u++) {
        const int pos = topS[u];
        const int pi  = (bh * UU + u) * NS + c;
        if (k0 > pos) {   // fully masked chunk (block-uniform branch)
            if (t == 0) { g_pm[pi] = -INFINITY; g_pl[pi] = 0.f; }
            continue;
        }
        const int pb = u & 1;
        const int kg = k0 + t;

        float a0 = 0.f, a1 = 0.f, a2 = 0.f, a3 = 0.f;
#pragma unroll
        for (int j = 0; j < 16; j++) {
            const float4 kv = kreg[j];
            const float4 qv = *(const float4*)&Qs[u][j * 4];
            a0 += kv.x * qv.x; a1 += kv.y * qv.y;
            a2 += kv.z * qv.z; a3 += kv.w * qv.w;
        }
        float s = ((a0 + a1) + (a2 + a3)) * 0.125f;   // 1/sqrt(64)
        if (kg > pos) s = -INFINITY;

        float m = s;
#pragma unroll
        for (int off = 16; off; off >>= 1) m = fmaxf(m, __shfl_xor_sync(0xffffffffu, m, off));
        if (lane == 0) redm[wid] = m;
        __syncthreads();   // B
        m = fmaxf(redm[0], redm[1]);   // finite: key k0 is unmasked

        const float p = (kg <= pos) ? __expf(s - m) : 0.f;
        ps[pb][t] = p;
        float l = p;
#pragma unroll
        for (int off = 16; off; off >>= 1) l += __shfl_xor_sync(0xffffffffu, l, off);
        if (lane == 0) redl[wid] = l;
        __syncthreads();   // C: ps[pb] visible
        l = redl[0] + redl[1];

        float acc = 0.f;
#pragma unroll
        for (int k = 0; k < CK; k++) acc += ps[pb][k] * vreg[k];
        g_pacc[(size_t)pi * DD + t] = acc;
        if (t == 0) { g_pm[pi] = m; g_pl[pi] = l; }
    }
}

// ---------------------------------------------------------------------------
// Kernel 5: combine partials (log-sum-exp) and scatter into d_out.
// grid = BH*UU, block = 64 (thread = dim).
// ---------------------------------------------------------------------------
__global__ void combine_kernel(float* __restrict__ out) {
    const int bhu = blockIdx.x;
    const int t   = threadIdx.x;
    const int bh  = bhu / UU;
    const int pos = g_top[bhu];

    float mx = -INFINITY;
#pragma unroll
    for (int c = 0; c < NS; c++) mx = fmaxf(mx, g_pm[bhu * NS + c]);

    float Ls = 0.f, acc = 0.f;
#pragma unroll
    for (int c = 0; c < NS; c++) {
        const float plv = g_pl[bhu * NS + c];
        if (plv > 0.f) {
            const float w = __expf(g_pm[bhu * NS + c] - mx);
            Ls  += plv * w;
            acc += w * g_pacc[(size_t)(bhu * NS + c) * DD + t];
        }
    }
    out[(size_t)bh * LL * DD + (size_t)pos * DD + t] = acc / Ls;
}

// ---------------------------------------------------------------------------
extern "C" void kernel_launch(void* const* d_in, const int* in_sizes, int n_in,
                              void* d_out, int out_size) {
    const float* Q   = (const float*)d_in[0];
    const float* K   = (const float*)d_in[1];
    const float* V   = (const float*)d_in[2];
    const int*   idx = (const int*)d_in[3];
    float* out = (float*)d_out;

    cumsum_kernel<<<BH * 4, 1024>>>(V, out);
    m_kernel<<<BH * LL / 8, 256>>>(Q, K, idx);
    topk_kernel<<<BH, 256>>>();
    attn_partial_kernel<<<BH * NS, CK>>>(Q, K, V);
    combine_kernel<<<BH * UU, DD>>>(out);
}